// round 1
// baseline (speedup 1.0000x reference)
#include <cuda_runtime.h>
#include <cuda_fp16.h>
#include <cstdint>

#define BM 64          // q rows per CTA
#define BN 64          // kv rows per tile
#define HD 128         // head dim
#define LDS 136        // smem halves per row (128 + 8 pad -> 272B row, 16B aligned, ldmatrix conflict-free)
#define NTHREADS 128
#define SEQ 2048
#define BH 32          // B*H

__device__ __forceinline__ uint32_t cvta_smem(const void* p) {
    return (uint32_t)__cvta_generic_to_shared(p);
}

__device__ __forceinline__ void ldmx4(uint32_t addr, uint32_t &r0, uint32_t &r1, uint32_t &r2, uint32_t &r3) {
    asm volatile("ldmatrix.sync.aligned.m8n8.x4.shared.b16 {%0,%1,%2,%3}, [%4];"
                 : "=r"(r0), "=r"(r1), "=r"(r2), "=r"(r3) : "r"(addr));
}
__device__ __forceinline__ void ldmx4t(uint32_t addr, uint32_t &r0, uint32_t &r1, uint32_t &r2, uint32_t &r3) {
    asm volatile("ldmatrix.sync.aligned.m8n8.x4.trans.shared.b16 {%0,%1,%2,%3}, [%4];"
                 : "=r"(r0), "=r"(r1), "=r"(r2), "=r"(r3) : "r"(addr));
}
__device__ __forceinline__ void mma16816(float* c, uint32_t a0, uint32_t a1, uint32_t a2, uint32_t a3,
                                         uint32_t b0, uint32_t b1) {
    asm volatile("mma.sync.aligned.m16n8k16.row.col.f32.f16.f16.f32 "
                 "{%0,%1,%2,%3}, {%4,%5,%6,%7}, {%8,%9}, {%0,%1,%2,%3};"
                 : "+f"(c[0]), "+f"(c[1]), "+f"(c[2]), "+f"(c[3])
                 : "r"(a0), "r"(a1), "r"(a2), "r"(a3), "r"(b0), "r"(b1));
}

__global__ void __launch_bounds__(NTHREADS, 2)
fa_fwd(const float* __restrict__ Q, const float* __restrict__ K, const float* __restrict__ V,
       const float* __restrict__ qs, const float* __restrict__ ks, const float* __restrict__ vs,
       float* __restrict__ Out)
{
    extern __shared__ __half smem[];
    __half* sQ = smem;                 // BM x LDS
    __half* sK = smem + BM * LDS;      // BN x LDS
    __half* sV = smem + (BM + BN) * LDS;

    const int tid  = threadIdx.x;
    const int lane = tid & 31;
    const int warp = tid >> 5;
    const int qtile = blockIdx.x;
    const int bh    = blockIdx.y;

    const float qk_scale = qs[0] * ks[0] * 0.088388347648318447f; // 1/sqrt(128)
    const float vscale   = vs[0];

    const size_t base = (size_t)bh * SEQ * HD;
    const float* qg = Q + base + (size_t)qtile * BM * HD;
    const float* kg = K + base;
    const float* vg = V + base;
    float*       og = Out + base + (size_t)qtile * BM * HD;

    // ---- load Q tile (fp32 -> fp16, exact for fp8-representable values) ----
    for (int i = tid; i < BM * (HD / 4); i += NTHREADS) {
        int r = i >> 5;
        int c = (i & 31) << 2;
        float4 f = *(const float4*)(qg + (size_t)r * HD + c);
        __half2* d = (__half2*)(sQ + r * LDS + c);
        d[0] = __floats2half2_rn(f.x, f.y);
        d[1] = __floats2half2_rn(f.z, f.w);
    }

    float oacc[16][4];
    #pragma unroll
    for (int i = 0; i < 16; i++)
        #pragma unroll
        for (int j = 0; j < 4; j++) oacc[i][j] = 0.f;
    float m_i[2] = {-1e30f, -1e30f};
    float l_i[2] = {0.f, 0.f};

    // ldmatrix addressing (per-thread constants)
    const int a_row     = warp * 16 + (lane & 15);
    const int a_colbase = (lane >> 4) << 3;
    const int g = lane >> 3;
    const int b_row_off = ((g >> 1) << 3) + (lane & 7);  // K: n offset within 16-block
    const int b_col_off = (g & 1) << 3;                  // K: k offset within 16-block
    const int v_row_off = ((g & 1) << 3) + (lane & 7);   // V(trans): kv offset
    const int v_col_off = (g >> 1) << 3;                 // V(trans): d offset

    const int NTILES = SEQ / BN;
    for (int t = 0; t < NTILES; t++) {
        __syncthreads();   // previous compute done (and Q ready on first iter)
        // ---- load K and V tiles ----
        const float* kp = kg + (size_t)t * BN * HD;
        const float* vp = vg + (size_t)t * BN * HD;
        for (int i = tid; i < BN * (HD / 4); i += NTHREADS) {
            int r = i >> 5;
            int c = (i & 31) << 2;
            float4 fk = *(const float4*)(kp + (size_t)r * HD + c);
            __half2* dk = (__half2*)(sK + r * LDS + c);
            dk[0] = __floats2half2_rn(fk.x, fk.y);
            dk[1] = __floats2half2_rn(fk.z, fk.w);
            float4 fv = *(const float4*)(vp + (size_t)r * HD + c);
            __half2* dv = (__half2*)(sV + r * LDS + c);
            dv[0] = __floats2half2_rn(fv.x, fv.y);
            dv[1] = __floats2half2_rn(fv.z, fv.w);
        }
        __syncthreads();

        // ---- S = Q K^T (fp16 in, fp32 accum; exact since inputs fp8-representable) ----
        float sacc[8][4];
        #pragma unroll
        for (int i = 0; i < 8; i++)
            #pragma unroll
            for (int j = 0; j < 4; j++) sacc[i][j] = 0.f;

        #pragma unroll
        for (int kk = 0; kk < 8; kk++) {
            uint32_t a0, a1, a2, a3;
            ldmx4(cvta_smem(sQ + a_row * LDS + a_colbase + kk * 16), a0, a1, a2, a3);
            #pragma unroll
            for (int np = 0; np < 4; np++) {
                uint32_t b0, b1, b2, b3;
                ldmx4(cvta_smem(sK + (np * 16 + b_row_off) * LDS + b_col_off + kk * 16),
                      b0, b1, b2, b3);
                mma16816(sacc[2 * np],     a0, a1, a2, a3, b0, b1);
                mma16816(sacc[2 * np + 1], a0, a1, a2, a3, b2, b3);
            }
        }

        // ---- online softmax (scale applied in fp32 AFTER exact MMA) ----
        float rmax[2] = {-1e30f, -1e30f};
        #pragma unroll
        for (int nt = 0; nt < 8; nt++) {
            sacc[nt][0] *= qk_scale; sacc[nt][1] *= qk_scale;
            sacc[nt][2] *= qk_scale; sacc[nt][3] *= qk_scale;
            rmax[0] = fmaxf(rmax[0], fmaxf(sacc[nt][0], sacc[nt][1]));
            rmax[1] = fmaxf(rmax[1], fmaxf(sacc[nt][2], sacc[nt][3]));
        }
        #pragma unroll
        for (int x = 1; x < 4; x <<= 1) {
            rmax[0] = fmaxf(rmax[0], __shfl_xor_sync(0xffffffffu, rmax[0], x));
            rmax[1] = fmaxf(rmax[1], __shfl_xor_sync(0xffffffffu, rmax[1], x));
        }
        float mnew[2]  = { fmaxf(m_i[0], rmax[0]), fmaxf(m_i[1], rmax[1]) };
        float alpha[2] = { __expf(m_i[0] - mnew[0]), __expf(m_i[1] - mnew[1]) };

        float psum[2] = {0.f, 0.f};
        uint32_t pfrag[8][2];
        #pragma unroll
        for (int nt = 0; nt < 8; nt++) {
            float p0 = __expf(sacc[nt][0] - mnew[0]);
            float p1 = __expf(sacc[nt][1] - mnew[0]);
            float p2 = __expf(sacc[nt][2] - mnew[1]);
            float p3 = __expf(sacc[nt][3] - mnew[1]);
            psum[0] += p0 + p1;
            psum[1] += p2 + p3;
            __half2 h0 = __floats2half2_rn(p0, p1);
            __half2 h1 = __floats2half2_rn(p2, p3);
            pfrag[nt][0] = reinterpret_cast<uint32_t&>(h0);
            pfrag[nt][1] = reinterpret_cast<uint32_t&>(h1);
        }
        #pragma unroll
        for (int x = 1; x < 4; x <<= 1) {
            psum[0] += __shfl_xor_sync(0xffffffffu, psum[0], x);
            psum[1] += __shfl_xor_sync(0xffffffffu, psum[1], x);
        }
        l_i[0] = l_i[0] * alpha[0] + psum[0];
        l_i[1] = l_i[1] * alpha[1] + psum[1];
        m_i[0] = mnew[0];
        m_i[1] = mnew[1];

        #pragma unroll
        for (int nt = 0; nt < 16; nt++) {
            oacc[nt][0] *= alpha[0]; oacc[nt][1] *= alpha[0];
            oacc[nt][2] *= alpha[1]; oacc[nt][3] *= alpha[1];
        }

        // ---- O += P V  (P stays in registers: C-fragment == A-fragment layout) ----
        #pragma unroll
        for (int kk = 0; kk < 4; kk++) {
            uint32_t a0 = pfrag[2 * kk][0];
            uint32_t a1 = pfrag[2 * kk][1];
            uint32_t a2 = pfrag[2 * kk + 1][0];
            uint32_t a3 = pfrag[2 * kk + 1][1];
            #pragma unroll
            for (int np = 0; np < 8; np++) {
                uint32_t b0, b1, b2, b3;
                ldmx4t(cvta_smem(sV + (kk * 16 + v_row_off) * LDS + np * 16 + v_col_off),
                       b0, b1, b2, b3);
                mma16816(oacc[2 * np],     a0, a1, a2, a3, b0, b1);
                mma16816(oacc[2 * np + 1], a0, a1, a2, a3, b2, b3);
            }
        }
    }

    // ---- epilogue: normalize + vs dequant, fp32 out ----
    const float inv0 = vscale / l_i[0];
    const float inv1 = vscale / l_i[1];
    const int row = warp * 16 + (lane >> 2);
    const int c0  = (lane & 3) * 2;
    #pragma unroll
    for (int nt = 0; nt < 16; nt++) {
        float2 lo = { oacc[nt][0] * inv0, oacc[nt][1] * inv0 };
        float2 hi = { oacc[nt][2] * inv1, oacc[nt][3] * inv1 };
        *(float2*)(og + (size_t)row * HD + nt * 8 + c0)       = lo;
        *(float2*)(og + (size_t)(row + 8) * HD + nt * 8 + c0) = hi;
    }
}

extern "C" void kernel_launch(void* const* d_in, const int* in_sizes, int n_in,
                              void* d_out, int out_size) {
    // inputs (metadata order): s, q, k, v, qs, ks, vs — all float32
    const float* q  = (const float*)d_in[1];
    const float* k  = (const float*)d_in[2];
    const float* v  = (const float*)d_in[3];
    const float* qs = (const float*)d_in[4];
    const float* ks = (const float*)d_in[5];
    const float* vs = (const float*)d_in[6];
    float* out = (float*)d_out;

    const int smem_bytes = (BM + BN + BN) * LDS * (int)sizeof(__half); // 52224
    cudaFuncSetAttribute(fa_fwd, cudaFuncAttributeMaxDynamicSharedMemorySize, smem_bytes);

    dim3 grid(SEQ / BM, BH);   // (32 q-tiles, 32 batch-heads)
    fa_fwd<<<grid, NTHREADS, smem_bytes>>>(q, k, v, qs, ks, vs, out);
}

// round 3
// speedup vs baseline: 2.3158x; 2.3158x over previous
#include <cuda_runtime.h>
#include <cuda_fp16.h>
#include <cstdint>

#define HD   128
#define BM   64
#define BN   64
#define SEQ  2048
#define BH   32
#define NTH  128
#define NT   (SEQ / BN)      // 32 kv tiles
#define ELEMS (BH * SEQ * HD) // 8388608 per tensor

// fp16 copies of Q/K/V (fp8-exact values -> conversion is lossless)
__device__ __half gQ[ELEMS];
__device__ __half gK[ELEMS];
__device__ __half gV[ELEMS];

// smem byte offsets: Q (16KB) + K double (32KB) + V double (32KB) = 80KB
#define OQ   0
#define OK0  16384
#define OK1  32768
#define OV0  49152
#define OV1  65536
#define SMEMB 81920

static __device__ __forceinline__ void ldmx4(uint32_t a, uint32_t& r0, uint32_t& r1, uint32_t& r2, uint32_t& r3) {
    asm volatile("ldmatrix.sync.aligned.m8n8.x4.shared.b16 {%0,%1,%2,%3}, [%4];"
                 : "=r"(r0), "=r"(r1), "=r"(r2), "=r"(r3) : "r"(a));
}
static __device__ __forceinline__ void ldmx4t(uint32_t a, uint32_t& r0, uint32_t& r1, uint32_t& r2, uint32_t& r3) {
    asm volatile("ldmatrix.sync.aligned.m8n8.x4.trans.shared.b16 {%0,%1,%2,%3}, [%4];"
                 : "=r"(r0), "=r"(r1), "=r"(r2), "=r"(r3) : "r"(a));
}
static __device__ __forceinline__ void mma16816(float* c, const uint32_t* a, uint32_t b0, uint32_t b1) {
    asm volatile("mma.sync.aligned.m16n8k16.row.col.f32.f16.f16.f32 "
                 "{%0,%1,%2,%3}, {%4,%5,%6,%7}, {%8,%9}, {%0,%1,%2,%3};"
                 : "+f"(c[0]), "+f"(c[1]), "+f"(c[2]), "+f"(c[3])
                 : "r"(a[0]), "r"(a[1]), "r"(a[2]), "r"(a[3]), "r"(b0), "r"(b1));
}
static __device__ __forceinline__ void cpa16(uint32_t dst, const void* src) {
    asm volatile("cp.async.cg.shared.global [%0], [%1], 16;" :: "r"(dst), "l"(src) : "memory");
}
#define CP_COMMIT() asm volatile("cp.async.commit_group;" ::: "memory")
#define CP_WAIT1()  asm volatile("cp.async.wait_group 1;" ::: "memory")

static __device__ __forceinline__ float ex2f(float x) {
    float y; asm("ex2.approx.f32 %0, %1;" : "=f"(y) : "f"(x)); return y;
}

// load one 64x128 fp16 tile, row = 256B, XOR-swizzled: chunk' = chunk ^ (row&7)
static __device__ __forceinline__ void load_tile(uint32_t sdst, const __half* __restrict__ src, int tid) {
    #pragma unroll
    for (int j = 0; j < 8; j++) {
        int idx = j * 128 + tid;           // 0..1023 16B-chunks
        int row = idx >> 4, cc = idx & 15;
        uint32_t off = (uint32_t)(row << 8) + (uint32_t)(((cc ^ (row & 7)) << 4));
        cpa16(sdst + off, src + (size_t)row * HD + cc * 8);
    }
}

// ---------------- pre-pass: fp32 -> fp16 ----------------
__global__ void __launch_bounds__(256)
cvt_all(const float* __restrict__ q, const float* __restrict__ k, const float* __restrict__ v) {
    const float* src = (blockIdx.z == 0) ? q : (blockIdx.z == 1) ? k : v;
    __half* dst = (blockIdx.z == 0) ? gQ : (blockIdx.z == 1) ? gK : gV;
    int stride = gridDim.x * blockDim.x;
    for (int i = blockIdx.x * blockDim.x + threadIdx.x; i < ELEMS / 8; i += stride) {
        float4 f0 = ((const float4*)src)[2 * i];
        float4 f1 = ((const float4*)src)[2 * i + 1];
        __half2 h[4];
        h[0] = __floats2half2_rn(f0.x, f0.y);
        h[1] = __floats2half2_rn(f0.z, f0.w);
        h[2] = __floats2half2_rn(f1.x, f1.y);
        h[3] = __floats2half2_rn(f1.z, f1.w);
        ((uint4*)dst)[i] = *(uint4*)h;
    }
}

// ---------------- main attention ----------------
__global__ void __launch_bounds__(NTH, 2)
fa2(const float* __restrict__ qsp, const float* __restrict__ ksp, const float* __restrict__ vsp,
    float* __restrict__ Out)
{
    extern __shared__ char sm[];
    const uint32_t sb = (uint32_t)__cvta_generic_to_shared(sm);
    const int tid = threadIdx.x, lane = tid & 31, warp = tid >> 5;
    const int qt = blockIdx.x, bh = blockIdx.y;
    const size_t base = (size_t)bh * SEQ * HD;
    const __half* kg = gK + base;
    const __half* vg = gV + base;

    // prologue: Q + first two K/V tiles in flight
    load_tile(sb + OQ,  gQ + base + (size_t)qt * BM * HD, tid);
    load_tile(sb + OK0, kg, tid);
    load_tile(sb + OV0, vg, tid);
    CP_COMMIT();
    load_tile(sb + OK1, kg + BN * HD, tid);
    load_tile(sb + OV1, vg + BN * HD, tid);
    CP_COMMIT();
    CP_WAIT1();            // Q, K0, V0 resident
    __syncthreads();

    // hoist Q fragments for all 8 k-steps (reused across all 32 tiles)
    uint32_t qf[8][4];
    {
        const int ar  = warp * 16 + (lane & 15);
        const int ahi = lane >> 4;
        const uint32_t abase = sb + OQ + (uint32_t)(ar << 8);
        const int arx = ar & 7;
        #pragma unroll
        for (int kk = 0; kk < 8; kk++) {
            uint32_t a = abase + (uint32_t)((((kk << 1) + ahi) ^ arx) << 4);
            ldmx4(a, qf[kk][0], qf[kk][1], qf[kk][2], qf[kk][3]);
        }
    }

    const float cl = qsp[0] * ksp[0] * 0.088388347648318447f * 1.4426950408889634f; // scale*log2e
    const float vscale = vsp[0];

    float oacc[16][4];
    #pragma unroll
    for (int i = 0; i < 16; i++)
        #pragma unroll
        for (int j = 0; j < 4; j++) oacc[i][j] = 0.f;
    float m_i[2] = {-1e30f, -1e30f};
    float l_i[2] = {0.f, 0.f};

    const int g = lane >> 3;
    const int brow_off   = ((g >> 1) << 3) + (lane & 7);
    const int bchunk_off = g & 1;
    const int vrow_off   = ((g & 1) << 3) + (lane & 7);
    const int vchunk_off = g >> 1;

    for (int t = 0; t < NT; t++) {
        const uint32_t kbuf = sb + ((t & 1) ? OK1 : OK0);
        const uint32_t vbuf = sb + ((t & 1) ? OV1 : OV0);

        // ---- S = Q K^T ----
        float sacc[8][4];
        #pragma unroll
        for (int i = 0; i < 8; i++)
            #pragma unroll
            for (int j = 0; j < 4; j++) sacc[i][j] = 0.f;

        #pragma unroll
        for (int kk = 0; kk < 8; kk++) {
            #pragma unroll
            for (int np = 0; np < 4; np++) {
                int br = np * 16 + brow_off;
                uint32_t a = kbuf + (uint32_t)(br << 8)
                           + (uint32_t)((((kk << 1) + bchunk_off) ^ (br & 7)) << 4);
                uint32_t b0, b1, b2, b3;
                ldmx4(a, b0, b1, b2, b3);
                mma16816(sacc[2 * np],     qf[kk], b0, b1);
                mma16816(sacc[2 * np + 1], qf[kk], b2, b3);
            }
        }

        // ---- online softmax (scale folded into ex2) ----
        float rmax[2] = {-1e30f, -1e30f};
        #pragma unroll
        for (int nt = 0; nt < 8; nt++) {
            rmax[0] = fmaxf(rmax[0], fmaxf(sacc[nt][0], sacc[nt][1]));
            rmax[1] = fmaxf(rmax[1], fmaxf(sacc[nt][2], sacc[nt][3]));
        }
        #pragma unroll
        for (int x = 1; x < 4; x <<= 1) {
            rmax[0] = fmaxf(rmax[0], __shfl_xor_sync(0xffffffffu, rmax[0], x));
            rmax[1] = fmaxf(rmax[1], __shfl_xor_sync(0xffffffffu, rmax[1], x));
        }
        float mnew[2]  = { fmaxf(m_i[0], rmax[0]), fmaxf(m_i[1], rmax[1]) };
        float alpha[2] = { ex2f((m_i[0] - mnew[0]) * cl), ex2f((m_i[1] - mnew[1]) * cl) };

        float psum[2] = {0.f, 0.f};
        uint32_t pfrag[8][2];
        #pragma unroll
        for (int nt = 0; nt < 8; nt++) {
            float p0 = ex2f((sacc[nt][0] - mnew[0]) * cl);
            float p1 = ex2f((sacc[nt][1] - mnew[0]) * cl);
            float p2 = ex2f((sacc[nt][2] - mnew[1]) * cl);
            float p3 = ex2f((sacc[nt][3] - mnew[1]) * cl);
            psum[0] += p0 + p1;
            psum[1] += p2 + p3;
            __half2 h0 = __floats2half2_rn(p0, p1);
            __half2 h1 = __floats2half2_rn(p2, p3);
            pfrag[nt][0] = *(uint32_t*)&h0;
            pfrag[nt][1] = *(uint32_t*)&h1;
        }
        #pragma unroll
        for (int x = 1; x < 4; x <<= 1) {
            psum[0] += __shfl_xor_sync(0xffffffffu, psum[0], x);
            psum[1] += __shfl_xor_sync(0xffffffffu, psum[1], x);
        }
        l_i[0] = l_i[0] * alpha[0] + psum[0];
        l_i[1] = l_i[1] * alpha[1] + psum[1];
        m_i[0] = mnew[0];
        m_i[1] = mnew[1];

        #pragma unroll
        for (int nt = 0; nt < 16; nt++) {
            oacc[nt][0] *= alpha[0]; oacc[nt][1] *= alpha[0];
            oacc[nt][2] *= alpha[1]; oacc[nt][3] *= alpha[1];
        }

        // ---- O += P V ----
        #pragma unroll
        for (int kk = 0; kk < 4; kk++) {
            uint32_t pa[4] = { pfrag[2 * kk][0], pfrag[2 * kk][1],
                               pfrag[2 * kk + 1][0], pfrag[2 * kk + 1][1] };
            int vr = kk * 16 + vrow_off;
            uint32_t vb = vbuf + (uint32_t)(vr << 8);
            int vrx = vr & 7;
            #pragma unroll
            for (int np = 0; np < 8; np++) {
                uint32_t a = vb + (uint32_t)((((np << 1) + vchunk_off) ^ vrx) << 4);
                uint32_t b0, b1, b2, b3;
                ldmx4t(a, b0, b1, b2, b3);
                mma16816(oacc[2 * np],     pa, b0, b1);
                mma16816(oacc[2 * np + 1], pa, b2, b3);
            }
        }

        // ---- prefetch tile t+2 into the buffer we just finished ----
        __syncthreads();
        if (t + 2 < NT) {
            load_tile(kbuf, kg + (size_t)(t + 2) * BN * HD, tid);
            load_tile(vbuf, vg + (size_t)(t + 2) * BN * HD, tid);
        }
        CP_COMMIT();
        CP_WAIT1();          // tile t+1 guaranteed resident
        __syncthreads();
    }

    // ---- epilogue ----
    const float inv0 = vscale / l_i[0];
    const float inv1 = vscale / l_i[1];
    float* og = Out + base + (size_t)qt * BM * HD;
    const int row = warp * 16 + (lane >> 2);
    const int c0  = (lane & 3) * 2;
    #pragma unroll
    for (int nt = 0; nt < 16; nt++) {
        float2 lo = { oacc[nt][0] * inv0, oacc[nt][1] * inv0 };
        float2 hi = { oacc[nt][2] * inv1, oacc[nt][3] * inv1 };
        *(float2*)(og + (size_t)row * HD + nt * 8 + c0)       = lo;
        *(float2*)(og + (size_t)(row + 8) * HD + nt * 8 + c0) = hi;
    }
}

extern "C" void kernel_launch(void* const* d_in, const int* in_sizes, int n_in,
                              void* d_out, int out_size) {
    const float* q  = (const float*)d_in[1];
    const float* k  = (const float*)d_in[2];
    const float* v  = (const float*)d_in[3];
    const float* qs = (const float*)d_in[4];
    const float* ks = (const float*)d_in[5];
    const float* vs = (const float*)d_in[6];
    float* out = (float*)d_out;

    dim3 cgrid(256, 1, 3);
    cvt_all<<<cgrid, 256>>>(q, k, v);

    cudaFuncSetAttribute(fa2, cudaFuncAttributeMaxDynamicSharedMemorySize, SMEMB);
    dim3 grid(SEQ / BM, BH);
    fa2<<<grid, NTH, SMEMB>>>(qs, ks, vs, out);
}